// round 11
// baseline (speedup 1.0000x reference)
#include <cuda_runtime.h>
#include <math.h>
#include <stdint.h>

#define T_TOK 3136
#define DIM   512
#define NH    8
#define HD    64
#define S_TOK 196
#define QT    56
#define NTILES (T_TOK / QT)   // 56

// Scratch (no allocations allowed)
__device__ float g_q[T_TOK * DIM];
__device__ float g_k[T_TOK * DIM];
__device__ float g_v[T_TOK * DIM];
__device__ float g_att[T_TOK * DIM];

__device__ __forceinline__ float to_tf32(float x) {
    uint32_t u;
    asm("cvt.rna.tf32.f32 %0, %1;" : "=r"(u) : "f"(x));
    return __uint_as_float(u);
}

__device__ __forceinline__ void mma_tf32(float* d, const uint32_t* a,
                                         uint32_t b0, uint32_t b1) {
    asm volatile(
        "mma.sync.aligned.m16n8k8.row.col.f32.tf32.tf32.f32 "
        "{%0,%1,%2,%3}, {%4,%5,%6,%7}, {%8,%9}, {%0,%1,%2,%3};\n"
        : "+f"(d[0]), "+f"(d[1]), "+f"(d[2]), "+f"(d[3])
        : "r"(a[0]), "r"(a[1]), "r"(a[2]), "r"(a[3]), "r"(b0), "r"(b1));
}

// ---------------------------------------------------------------------------
// TF32 GEMM (unchanged from R10): C[3136,512] = (A(+P)) @ W + bias
// ---------------------------------------------------------------------------
#define BM 128
#define BN 128
#define BK 16
#define SA_STR 20
#define SB_STR 136

__device__ __forceinline__ void gemm_tf32(const float* __restrict__ A,
                                          const float* __restrict__ P,
                                          const float* __restrict__ W,
                                          const float* __restrict__ bias,
                                          float* __restrict__ Cout) {
    __shared__ float sA[2][BM * SA_STR];
    __shared__ float sB[2][BK * SB_STR];

    const int tid = threadIdx.x;
    const int lane = tid & 31;
    const int warp = tid >> 5;
    const int warp_m = warp >> 2;
    const int warp_n = warp & 3;
    const int gr = lane >> 2;
    const int c  = lane & 3;
    const int m0 = blockIdx.y * BM;
    const int n0 = blockIdx.x * BN;

    const int arow = tid >> 2, acol = (tid & 3) * 4;
    const int brow = tid >> 5, bcol = (tid & 31) * 4;

    float acc[4][4][4];
#pragma unroll
    for (int mt = 0; mt < 4; mt++)
#pragma unroll
        for (int nt = 0; nt < 4; nt++)
#pragma unroll
            for (int r = 0; r < 4; r++) acc[mt][nt][r] = 0.f;

#pragma unroll
    for (int it2 = 0; it2 < 2; it2++) {
        int grow = m0 + arow + it2 * 64;
        if (grow > T_TOK - 1) grow = T_TOK - 1;
        float4 af = *reinterpret_cast<const float4*>(&A[grow * DIM + acol]);
        if (P) {
            float4 pf = *reinterpret_cast<const float4*>(&P[grow * DIM + acol]);
            af.x += pf.x; af.y += pf.y; af.z += pf.z; af.w += pf.w;
        }
        *reinterpret_cast<float4*>(&sA[0][(arow + it2 * 64) * SA_STR + acol]) =
            make_float4(to_tf32(af.x), to_tf32(af.y), to_tf32(af.z), to_tf32(af.w));
        float4 bf = *reinterpret_cast<const float4*>(&W[(brow + it2 * 8) * DIM + n0 + bcol]);
        *reinterpret_cast<float4*>(&sB[0][(brow + it2 * 8) * SB_STR + bcol]) =
            make_float4(to_tf32(bf.x), to_tf32(bf.y), to_tf32(bf.z), to_tf32(bf.w));
    }
    __syncthreads();

    int s = 0;
    const int NITER = DIM / BK;
    for (int it = 0; it < NITER; it++) {
        const int k0n = (it + 1) * BK;
        const bool has = (k0n < DIM);
        float4 af[2], bf[2];
        if (has) {
#pragma unroll
            for (int it2 = 0; it2 < 2; it2++) {
                int grow = m0 + arow + it2 * 64;
                if (grow > T_TOK - 1) grow = T_TOK - 1;
                af[it2] = *reinterpret_cast<const float4*>(&A[grow * DIM + k0n + acol]);
                if (P) {
                    float4 pf = *reinterpret_cast<const float4*>(&P[grow * DIM + k0n + acol]);
                    af[it2].x += pf.x; af[it2].y += pf.y;
                    af[it2].z += pf.z; af[it2].w += pf.w;
                }
                bf[it2] = *reinterpret_cast<const float4*>(
                    &W[(k0n + brow + it2 * 8) * DIM + n0 + bcol]);
            }
        }

#pragma unroll
        for (int ks = 0; ks < 2; ks++) {
            const int kb = ks * 8;
            uint32_t a[4][4];
#pragma unroll
            for (int mt = 0; mt < 4; mt++) {
                const float* ap = &sA[s][(warp_m * 64 + mt * 16 + gr) * SA_STR + kb + c];
                a[mt][0] = __float_as_uint(ap[0]);
                a[mt][1] = __float_as_uint(ap[8 * SA_STR]);
                a[mt][2] = __float_as_uint(ap[4]);
                a[mt][3] = __float_as_uint(ap[8 * SA_STR + 4]);
            }
#pragma unroll
            for (int nt = 0; nt < 4; nt++) {
                const float* bp = &sB[s][(kb + c) * SB_STR + warp_n * 32 + nt * 8 + gr];
                uint32_t b0 = __float_as_uint(bp[0]);
                uint32_t b1 = __float_as_uint(bp[4 * SB_STR]);
#pragma unroll
                for (int mt = 0; mt < 4; mt++)
                    mma_tf32(acc[mt][nt], a[mt], b0, b1);
            }
        }

        if (has) {
#pragma unroll
            for (int it2 = 0; it2 < 2; it2++) {
                *reinterpret_cast<float4*>(&sA[s ^ 1][(arow + it2 * 64) * SA_STR + acol]) =
                    make_float4(to_tf32(af[it2].x), to_tf32(af[it2].y),
                                to_tf32(af[it2].z), to_tf32(af[it2].w));
                *reinterpret_cast<float4*>(&sB[s ^ 1][(brow + it2 * 8) * SB_STR + bcol]) =
                    make_float4(to_tf32(bf[it2].x), to_tf32(bf[it2].y),
                                to_tf32(bf[it2].z), to_tf32(bf[it2].w));
            }
            __syncthreads();
            s ^= 1;
        }
    }

#pragma unroll
    for (int mt = 0; mt < 4; mt++) {
#pragma unroll
        for (int nt = 0; nt < 4; nt++) {
            const int col = n0 + warp_n * 32 + nt * 8 + 2 * c;
            const float b0 = bias[col], b1 = bias[col + 1];
            const int r0 = m0 + warp_m * 64 + mt * 16 + gr;
            if (r0 < T_TOK)
                *reinterpret_cast<float2*>(&Cout[r0 * DIM + col]) =
                    make_float2(acc[mt][nt][0] + b0, acc[mt][nt][1] + b1);
            if (r0 + 8 < T_TOK)
                *reinterpret_cast<float2*>(&Cout[(r0 + 8) * DIM + col]) =
                    make_float2(acc[mt][nt][2] + b0, acc[mt][nt][3] + b1);
        }
    }
}

__global__ void proj_qkv(const float* __restrict__ xq, const float* __restrict__ xk,
                         const float* __restrict__ pos,
                         const float* __restrict__ Wq, const float* __restrict__ bq,
                         const float* __restrict__ Wk, const float* __restrict__ bk,
                         const float* __restrict__ Wv, const float* __restrict__ bv) {
    const float *A, *P, *W, *bias;
    float* out;
    if (blockIdx.z == 0)      { A = xq; P = pos;     W = Wq; bias = bq; out = g_q; }
    else if (blockIdx.z == 1) { A = xk; P = pos;     W = Wk; bias = bk; out = g_k; }
    else                      { A = xk; P = nullptr; W = Wv; bias = bv; out = g_v; }
    gemm_tf32(A, P, W, bias, out);
}

__global__ void proj_o(const float* __restrict__ Wo, const float* __restrict__ bo,
                       float* __restrict__ out) {
    gemm_tf32(g_att, nullptr, Wo, bo, out);
}

// ---------------------------------------------------------------------------
// Attention v4: TF32 mma flash attention, 2-stage pipelined K/V.
//  - K stored ROW-MAJOR [key][d] stride 72 (no transpose/swizzle):
//    QK B-frag read sK[(nt*8+gr)*72 + ks*8+c] -> bank 8gr+8ks+c, bijective.
//  - QK mma loop ks-outer: 8 independent sfr accumulators in flight.
//  - Two K/V smem stages: tile i+1 LDG->STS issued before computing tile i;
//    one __syncthreads per tile. Smem 91KB -> 2 blocks/SM.
// ---------------------------------------------------------------------------
#define SQ_STR  68
#define SKV_STR 72
#define A4_SMEM_FLOATS (64 * SQ_STR + 4 * 64 * SKV_STR)
#define A4_SMEM_BYTES  (A4_SMEM_FLOATS * 4)   // 91136

__global__ void attn4(const int* __restrict__ channels) {
    extern __shared__ float sm[];
    float* sQ = sm;                          // 64 x 68 (reused as sP)
    float* sK[2] = { sQ + 64 * SQ_STR, sQ + 64 * SQ_STR + 64 * SKV_STR };
    float* sV[2] = { sK[1] + 64 * SKV_STR, sK[1] + 2 * 64 * SKV_STR };
    float* sP = sQ;

    const int tid  = threadIdx.x;
    const int lane = tid & 31;
    const int warp = tid >> 5;
    const int gr = lane >> 2;
    const int c  = lane & 3;
    const int h = blockIdx.y;
    const int qbase = blockIdx.x * QT;

    int off = 0, segs = 0, sege = 0;
#pragma unroll
    for (int i = 0; i < 4; i++) {
        int len = channels[i] * S_TOK;
        if (qbase >= off && qbase < off + len) { segs = off; sege = off + len; }
        off += len;
    }

    // Q tile: float4 loads, rows >= 56 zero-padded
#pragma unroll
    for (int i = tid; i < 64 * 16; i += 128) {
        int r = i >> 4, d = (i & 15) * 4;
        float4 v = make_float4(0.f, 0.f, 0.f, 0.f);
        if (r < QT)
            v = *reinterpret_cast<const float4*>(&g_q[(qbase + r) * DIM + h * HD + d]);
        *reinterpret_cast<float4*>(&sQ[r * SQ_STR + d]) =
            make_float4(to_tf32(v.x), to_tf32(v.y), to_tf32(v.z), to_tf32(v.w));
    }

    // preload tile 0 into stage 0 (no sync needed vs Q: disjoint regions)
    {
        int valid0 = sege - segs; if (valid0 > 64) valid0 = 64;
#pragma unroll
        for (int i = tid; i < 64 * 16; i += 128) {
            int r = i >> 4, d = (i & 15) * 4;
            float4 kv = make_float4(0.f, 0.f, 0.f, 0.f);
            float4 vv = make_float4(0.f, 0.f, 0.f, 0.f);
            if (r < valid0) {
                int base = (segs + r) * DIM + h * HD + d;
                kv = *reinterpret_cast<const float4*>(&g_k[base]);
                vv = *reinterpret_cast<const float4*>(&g_v[base]);
            }
            *reinterpret_cast<float4*>(&sK[0][r * SKV_STR + d]) =
                make_float4(to_tf32(kv.x), to_tf32(kv.y), to_tf32(kv.z), to_tf32(kv.w));
            *reinterpret_cast<float4*>(&sV[0][r * SKV_STR + d]) =
                make_float4(to_tf32(vv.x), to_tf32(vv.y), to_tf32(vv.z), to_tf32(vv.w));
        }
    }
    __syncthreads();

    // Hoist Q A-frags
    uint32_t qf[8][4];
#pragma unroll
    for (int ks = 0; ks < 8; ks++) {
        const float* ap = &sQ[(warp * 16 + gr) * SQ_STR + ks * 8 + c];
        qf[ks][0] = __float_as_uint(ap[0]);
        qf[ks][1] = __float_as_uint(ap[8 * SQ_STR]);
        qf[ks][2] = __float_as_uint(ap[4]);
        qf[ks][3] = __float_as_uint(ap[8 * SQ_STR + 4]);
    }
    // NOTE: sP (== sQ) is written only after this point in the first tile's
    // compute, which all warps reach only after __syncthreads above; the
    // qf hoist happens before any sP write in program order per warp, and
    // cross-warp sP regions are private. Safe.

    float m0 = -INFINITY, m1 = -INFINITY, l0 = 0.f, l1 = 0.f;
    float o[8][4];
#pragma unroll
    for (int nt = 0; nt < 8; nt++)
#pragma unroll
        for (int j = 0; j < 4; j++) o[nt][j] = 0.f;

    const float scale = 0.125f;
    int s = 0;

    for (int kb = segs; kb < sege; kb += 64, s ^= 1) {
        int valid = sege - kb; if (valid > 64) valid = 64;

        // ---- prefetch next tile into stage s^1 (overlaps with compute) ----
        if (kb + 64 < sege) {
            int nvalid = sege - (kb + 64); if (nvalid > 64) nvalid = 64;
#pragma unroll
            for (int i = tid; i < 64 * 16; i += 128) {
                int r = i >> 4, d = (i & 15) * 4;
                float4 kv = make_float4(0.f, 0.f, 0.f, 0.f);
                float4 vv = make_float4(0.f, 0.f, 0.f, 0.f);
                if (r < nvalid) {
                    int base = (kb + 64 + r) * DIM + h * HD + d;
                    kv = *reinterpret_cast<const float4*>(&g_k[base]);
                    vv = *reinterpret_cast<const float4*>(&g_v[base]);
                }
                *reinterpret_cast<float4*>(&sK[s ^ 1][r * SKV_STR + d]) =
                    make_float4(to_tf32(kv.x), to_tf32(kv.y), to_tf32(kv.z), to_tf32(kv.w));
                *reinterpret_cast<float4*>(&sV[s ^ 1][r * SKV_STR + d]) =
                    make_float4(to_tf32(vv.x), to_tf32(vv.y), to_tf32(vv.z), to_tf32(vv.w));
            }
        }

        // ---- S = Q K^T (ks-outer: 8 independent accumulators) ----
        float sfr[8][4];
#pragma unroll
        for (int nt = 0; nt < 8; nt++)
#pragma unroll
            for (int j = 0; j < 4; j++) sfr[nt][j] = 0.f;

#pragma unroll
        for (int ks = 0; ks < 8; ks++) {
#pragma unroll
            for (int nt = 0; nt < 8; nt++) {
                const float* bp = &sK[s][(nt * 8 + gr) * SKV_STR + ks * 8 + c];
                mma_tf32(sfr[nt], qf[ks],
                         __float_as_uint(bp[0]), __float_as_uint(bp[4]));
            }
        }

        // ---- scale + mask + warp-local online softmax ----
        float tmax0 = -INFINITY, tmax1 = -INFINITY;
#pragma unroll
        for (int nt = 0; nt < 8; nt++) {
            int col = nt * 8 + 2 * c;
            float s0 = sfr[nt][0] * scale, s1 = sfr[nt][1] * scale;
            float s2 = sfr[nt][2] * scale, s3 = sfr[nt][3] * scale;
            if (col     >= valid) { s0 = -1e30f; s2 = -1e30f; }
            if (col + 1 >= valid) { s1 = -1e30f; s3 = -1e30f; }
            sfr[nt][0] = s0; sfr[nt][1] = s1; sfr[nt][2] = s2; sfr[nt][3] = s3;
            tmax0 = fmaxf(tmax0, fmaxf(s0, s1));
            tmax1 = fmaxf(tmax1, fmaxf(s2, s3));
        }
        tmax0 = fmaxf(tmax0, __shfl_xor_sync(0xFFFFFFFFu, tmax0, 1));
        tmax0 = fmaxf(tmax0, __shfl_xor_sync(0xFFFFFFFFu, tmax0, 2));
        tmax1 = fmaxf(tmax1, __shfl_xor_sync(0xFFFFFFFFu, tmax1, 1));
        tmax1 = fmaxf(tmax1, __shfl_xor_sync(0xFFFFFFFFu, tmax1, 2));

        float mn0 = fmaxf(m0, tmax0), mn1 = fmaxf(m1, tmax1);
        float corr0 = __expf(m0 - mn0), corr1 = __expf(m1 - mn1);
        m0 = mn0; m1 = mn1;

        float ps0 = 0.f, ps1 = 0.f;
#pragma unroll
        for (int nt = 0; nt < 8; nt++) {
            float p0 = __expf(sfr[nt][0] - mn0);
            float p1 = __expf(sfr[nt][1] - mn0);
            float p2 = __expf(sfr[nt][2] - mn1);
            float p3 = __expf(sfr[nt][3] - mn1);
            sfr[nt][0] = p0; sfr[nt][1] = p1; sfr[nt][2] = p2; sfr[nt][3] = p3;
            ps0 += p0 + p1; ps1 += p2 + p3;
        }
        ps0 += __shfl_xor_sync(0xFFFFFFFFu, ps0, 1);
        ps0 += __shfl_xor_sync(0xFFFFFFFFu, ps0, 2);
        ps1 += __shfl_xor_sync(0xFFFFFFFFu, ps1, 1);
        ps1 += __shfl_xor_sync(0xFFFFFFFFu, ps1, 2);
        l0 = l0 * corr0 + ps0;
        l1 = l1 * corr1 + ps1;

#pragma unroll
        for (int nt = 0; nt < 8; nt++) {
            o[nt][0] *= corr0; o[nt][1] *= corr0;
            o[nt][2] *= corr1; o[nt][3] *= corr1;
        }

        // ---- spill P (tf32) to warp-private smem ----
        {
            float* pr0 = &sP[(warp * 16 + gr) * SQ_STR];
            float* pr1 = &sP[(warp * 16 + gr + 8) * SQ_STR];
#pragma unroll
            for (int nt = 0; nt < 8; nt++) {
                int col = nt * 8 + 2 * c;
                *reinterpret_cast<float2*>(pr0 + col) =
                    make_float2(to_tf32(sfr[nt][0]), to_tf32(sfr[nt][1]));
                *reinterpret_cast<float2*>(pr1 + col) =
                    make_float2(to_tf32(sfr[nt][2]), to_tf32(sfr[nt][3]));
            }
        }
        __syncwarp();

        // ---- O += P V (ks-outer, independent nt accumulators) ----
#pragma unroll
        for (int ks = 0; ks < 8; ks++) {
            const float* ap = &sP[(warp * 16 + gr) * SQ_STR + ks * 8 + c];
            uint32_t a[4];
            a[0] = __float_as_uint(ap[0]);
            a[1] = __float_as_uint(ap[8 * SQ_STR]);
            a[2] = __float_as_uint(ap[4]);
            a[3] = __float_as_uint(ap[8 * SQ_STR + 4]);
#pragma unroll
            for (int nt = 0; nt < 8; nt++) {
                const float* bp = &sV[s][(ks * 8 + c) * SKV_STR + nt * 8 + gr];
                mma_tf32(o[nt], a,
                         __float_as_uint(bp[0]),
                         __float_as_uint(bp[4 * SKV_STR]));
            }
        }

        __syncthreads();   // stage s free for reuse; stage s^1 stores visible
    }

    // ---- epilogue ----
    const int lr0 = warp * 16 + gr;
    const float inv0 = 1.f / l0, inv1 = 1.f / l1;
#pragma unroll
    for (int nt = 0; nt < 8; nt++) {
        int col = h * HD + nt * 8 + 2 * c;
        if (lr0 < QT)
            *reinterpret_cast<float2*>(&g_att[(qbase + lr0) * DIM + col]) =
                make_float2(o[nt][0] * inv0, o[nt][1] * inv0);
        if (lr0 + 8 < QT)
            *reinterpret_cast<float2*>(&g_att[(qbase + lr0 + 8) * DIM + col]) =
                make_float2(o[nt][2] * inv1, o[nt][3] * inv1);
    }
}

// ---------------------------------------------------------------------------
extern "C" void kernel_launch(void* const* d_in, const int* in_sizes, int n_in,
                              void* d_out, int out_size) {
    const float* xq  = (const float*)d_in[0];
    const float* xk  = (const float*)d_in[1];
    const float* pos = (const float*)d_in[2];
    const int*   channels = (const int*)d_in[3];
    const float* Wq = (const float*)d_in[4];  const float* bq = (const float*)d_in[5];
    const float* Wk = (const float*)d_in[6];  const float* bk = (const float*)d_in[7];
    const float* Wv = (const float*)d_in[8];  const float* bv = (const float*)d_in[9];
    const float* Wo = (const float*)d_in[10]; const float* bo = (const float*)d_in[11];

    cudaFuncSetAttribute(attn4, cudaFuncAttributeMaxDynamicSharedMemorySize,
                         A4_SMEM_BYTES);

    const int gy = (T_TOK + BM - 1) / BM;   // 25
    proj_qkv<<<dim3(DIM / BN, gy, 3), 256>>>(xq, xk, pos, Wq, bq, Wk, bk, Wv, bv);
    attn4<<<dim3(NTILES, NH), 128, A4_SMEM_BYTES>>>(channels);
    proj_o<<<dim3(DIM / BN, gy, 1), 256>>>(Wo, bo, (float*)d_out);
}

// round 12
// speedup vs baseline: 1.3059x; 1.3059x over previous
#include <cuda_runtime.h>
#include <math.h>
#include <stdint.h>

#define T_TOK 3136
#define DIM   512
#define NH    8
#define HD    64
#define S_TOK 196
#define QT    56
#define NTILES (T_TOK / QT)   // 56

// Scratch (no allocations allowed)
__device__ float g_q[T_TOK * DIM];
__device__ float g_k[T_TOK * DIM];
__device__ float g_v[T_TOK * DIM];
__device__ float g_att[T_TOK * DIM];

__device__ __forceinline__ float to_tf32(float x) {
    uint32_t u;
    asm("cvt.rna.tf32.f32 %0, %1;" : "=r"(u) : "f"(x));
    return __uint_as_float(u);
}

__device__ __forceinline__ void mma_tf32(float* d, const uint32_t* a,
                                         uint32_t b0, uint32_t b1) {
    asm volatile(
        "mma.sync.aligned.m16n8k8.row.col.f32.tf32.tf32.f32 "
        "{%0,%1,%2,%3}, {%4,%5,%6,%7}, {%8,%9}, {%0,%1,%2,%3};\n"
        : "+f"(d[0]), "+f"(d[1]), "+f"(d[2]), "+f"(d[3])
        : "r"(a[0]), "r"(a[1]), "r"(a[2]), "r"(a[3]), "r"(b0), "r"(b1));
}

// ---------------------------------------------------------------------------
// TF32 GEMM (unchanged from R10): C[3136,512] = (A(+P)) @ W + bias
// ---------------------------------------------------------------------------
#define BM 128
#define BN 128
#define BK 16
#define SA_STR 20
#define SB_STR 136

__device__ __forceinline__ void gemm_tf32(const float* __restrict__ A,
                                          const float* __restrict__ P,
                                          const float* __restrict__ W,
                                          const float* __restrict__ bias,
                                          float* __restrict__ Cout) {
    __shared__ float sA[2][BM * SA_STR];
    __shared__ float sB[2][BK * SB_STR];

    const int tid = threadIdx.x;
    const int lane = tid & 31;
    const int warp = tid >> 5;
    const int warp_m = warp >> 2;
    const int warp_n = warp & 3;
    const int gr = lane >> 2;
    const int c  = lane & 3;
    const int m0 = blockIdx.y * BM;
    const int n0 = blockIdx.x * BN;

    const int arow = tid >> 2, acol = (tid & 3) * 4;
    const int brow = tid >> 5, bcol = (tid & 31) * 4;

    float acc[4][4][4];
#pragma unroll
    for (int mt = 0; mt < 4; mt++)
#pragma unroll
        for (int nt = 0; nt < 4; nt++)
#pragma unroll
            for (int r = 0; r < 4; r++) acc[mt][nt][r] = 0.f;

#pragma unroll
    for (int it2 = 0; it2 < 2; it2++) {
        int grow = m0 + arow + it2 * 64;
        if (grow > T_TOK - 1) grow = T_TOK - 1;
        float4 af = *reinterpret_cast<const float4*>(&A[grow * DIM + acol]);
        if (P) {
            float4 pf = *reinterpret_cast<const float4*>(&P[grow * DIM + acol]);
            af.x += pf.x; af.y += pf.y; af.z += pf.z; af.w += pf.w;
        }
        *reinterpret_cast<float4*>(&sA[0][(arow + it2 * 64) * SA_STR + acol]) =
            make_float4(to_tf32(af.x), to_tf32(af.y), to_tf32(af.z), to_tf32(af.w));
        float4 bf = *reinterpret_cast<const float4*>(&W[(brow + it2 * 8) * DIM + n0 + bcol]);
        *reinterpret_cast<float4*>(&sB[0][(brow + it2 * 8) * SB_STR + bcol]) =
            make_float4(to_tf32(bf.x), to_tf32(bf.y), to_tf32(bf.z), to_tf32(bf.w));
    }
    __syncthreads();

    int s = 0;
    const int NITER = DIM / BK;
    for (int it = 0; it < NITER; it++) {
        const int k0n = (it + 1) * BK;
        const bool has = (k0n < DIM);
        float4 af[2], bf[2];
        if (has) {
#pragma unroll
            for (int it2 = 0; it2 < 2; it2++) {
                int grow = m0 + arow + it2 * 64;
                if (grow > T_TOK - 1) grow = T_TOK - 1;
                af[it2] = *reinterpret_cast<const float4*>(&A[grow * DIM + k0n + acol]);
                if (P) {
                    float4 pf = *reinterpret_cast<const float4*>(&P[grow * DIM + k0n + acol]);
                    af[it2].x += pf.x; af[it2].y += pf.y;
                    af[it2].z += pf.z; af[it2].w += pf.w;
                }
                bf[it2] = *reinterpret_cast<const float4*>(
                    &W[(k0n + brow + it2 * 8) * DIM + n0 + bcol]);
            }
        }

#pragma unroll
        for (int ks = 0; ks < 2; ks++) {
            const int kb = ks * 8;
            uint32_t a[4][4];
#pragma unroll
            for (int mt = 0; mt < 4; mt++) {
                const float* ap = &sA[s][(warp_m * 64 + mt * 16 + gr) * SA_STR + kb + c];
                a[mt][0] = __float_as_uint(ap[0]);
                a[mt][1] = __float_as_uint(ap[8 * SA_STR]);
                a[mt][2] = __float_as_uint(ap[4]);
                a[mt][3] = __float_as_uint(ap[8 * SA_STR + 4]);
            }
#pragma unroll
            for (int nt = 0; nt < 4; nt++) {
                const float* bp = &sB[s][(kb + c) * SB_STR + warp_n * 32 + nt * 8 + gr];
                uint32_t b0 = __float_as_uint(bp[0]);
                uint32_t b1 = __float_as_uint(bp[4 * SB_STR]);
#pragma unroll
                for (int mt = 0; mt < 4; mt++)
                    mma_tf32(acc[mt][nt], a[mt], b0, b1);
            }
        }

        if (has) {
#pragma unroll
            for (int it2 = 0; it2 < 2; it2++) {
                *reinterpret_cast<float4*>(&sA[s ^ 1][(arow + it2 * 64) * SA_STR + acol]) =
                    make_float4(to_tf32(af[it2].x), to_tf32(af[it2].y),
                                to_tf32(af[it2].z), to_tf32(af[it2].w));
                *reinterpret_cast<float4*>(&sB[s ^ 1][(brow + it2 * 8) * SB_STR + bcol]) =
                    make_float4(to_tf32(bf[it2].x), to_tf32(bf[it2].y),
                                to_tf32(bf[it2].z), to_tf32(bf[it2].w));
            }
            __syncthreads();
            s ^= 1;
        }
    }

#pragma unroll
    for (int mt = 0; mt < 4; mt++) {
#pragma unroll
        for (int nt = 0; nt < 4; nt++) {
            const int col = n0 + warp_n * 32 + nt * 8 + 2 * c;
            const float b0 = bias[col], b1 = bias[col + 1];
            const int r0 = m0 + warp_m * 64 + mt * 16 + gr;
            if (r0 < T_TOK)
                *reinterpret_cast<float2*>(&Cout[r0 * DIM + col]) =
                    make_float2(acc[mt][nt][0] + b0, acc[mt][nt][1] + b1);
            if (r0 + 8 < T_TOK)
                *reinterpret_cast<float2*>(&Cout[(r0 + 8) * DIM + col]) =
                    make_float2(acc[mt][nt][2] + b0, acc[mt][nt][3] + b1);
        }
    }
}

__global__ void proj_qkv(const float* __restrict__ xq, const float* __restrict__ xk,
                         const float* __restrict__ pos,
                         const float* __restrict__ Wq, const float* __restrict__ bq,
                         const float* __restrict__ Wk, const float* __restrict__ bk,
                         const float* __restrict__ Wv, const float* __restrict__ bv) {
    const float *A, *P, *W, *bias;
    float* out;
    if (blockIdx.z == 0)      { A = xq; P = pos;     W = Wq; bias = bq; out = g_q; }
    else if (blockIdx.z == 1) { A = xk; P = pos;     W = Wk; bias = bk; out = g_k; }
    else                      { A = xk; P = nullptr; W = Wv; bias = bv; out = g_v; }
    gemm_tf32(A, P, W, bias, out);
}

__global__ void proj_o(const float* __restrict__ Wo, const float* __restrict__ bo,
                       float* __restrict__ out) {
    gemm_tf32(g_att, nullptr, Wo, bo, out);
}

// ---------------------------------------------------------------------------
// Attention v5: TF32 mma flash attention. Single-stage (R10 occupancy: 54KB,
// 4 blocks/SM) + R11's two pure wins:
//  - K row-major [key][d] stride 72, float4 STS (no transpose, no conflicts);
//    QK B-frag read sK[(nt*8+gr)*72 + ks*8+c] -> bank 8gr+8ks+c, bijective.
//  - ks-outer mma loops: 8 independent accumulators in flight.
// ---------------------------------------------------------------------------
#define SQ_STR  68
#define SKV_STR 72
#define A5_SMEM_FLOATS (64 * SQ_STR + 2 * 64 * SKV_STR)
#define A5_SMEM_BYTES  (A5_SMEM_FLOATS * 4)   // 54272

__global__ void attn5(const int* __restrict__ channels) {
    extern __shared__ float sm[];
    float* sQ = sm;                      // 64 x 68 (reused as sP)
    float* sK = sQ + 64 * SQ_STR;        // 64 x 72 row-major
    float* sV = sK + 64 * SKV_STR;       // 64 x 72 row-major
    float* sP = sQ;

    const int tid  = threadIdx.x;
    const int lane = tid & 31;
    const int warp = tid >> 5;
    const int gr = lane >> 2;
    const int c  = lane & 3;
    const int h = blockIdx.y;
    const int qbase = blockIdx.x * QT;

    int off = 0, segs = 0, sege = 0;
#pragma unroll
    for (int i = 0; i < 4; i++) {
        int len = channels[i] * S_TOK;
        if (qbase >= off && qbase < off + len) { segs = off; sege = off + len; }
        off += len;
    }

    // Q tile: float4 loads, rows >= 56 zero-padded
#pragma unroll
    for (int i = tid; i < 64 * 16; i += 128) {
        int r = i >> 4, d = (i & 15) * 4;
        float4 v = make_float4(0.f, 0.f, 0.f, 0.f);
        if (r < QT)
            v = *reinterpret_cast<const float4*>(&g_q[(qbase + r) * DIM + h * HD + d]);
        *reinterpret_cast<float4*>(&sQ[r * SQ_STR + d]) =
            make_float4(to_tf32(v.x), to_tf32(v.y), to_tf32(v.z), to_tf32(v.w));
    }
    __syncthreads();

    // Hoist Q A-frags (constant across k-tiles)
    uint32_t qf[8][4];
#pragma unroll
    for (int ks = 0; ks < 8; ks++) {
        const float* ap = &sQ[(warp * 16 + gr) * SQ_STR + ks * 8 + c];
        qf[ks][0] = __float_as_uint(ap[0]);
        qf[ks][1] = __float_as_uint(ap[8 * SQ_STR]);
        qf[ks][2] = __float_as_uint(ap[4]);
        qf[ks][3] = __float_as_uint(ap[8 * SQ_STR + 4]);
    }

    float m0 = -INFINITY, m1 = -INFINITY, l0 = 0.f, l1 = 0.f;
    float o[8][4];
#pragma unroll
    for (int nt = 0; nt < 8; nt++)
#pragma unroll
        for (int j = 0; j < 4; j++) o[nt][j] = 0.f;

    const float scale = 0.125f;

    for (int kb = segs; kb < sege; kb += 64) {
        int valid = sege - kb; if (valid > 64) valid = 64;

        __syncthreads();   // prior tile's PV reads of sK/sV/sP complete
#pragma unroll
        for (int i = tid; i < 64 * 16; i += 128) {
            int r = i >> 4, d = (i & 15) * 4;
            float4 kv = make_float4(0.f, 0.f, 0.f, 0.f);
            float4 vv = make_float4(0.f, 0.f, 0.f, 0.f);
            if (r < valid) {
                int base = (kb + r) * DIM + h * HD + d;
                kv = *reinterpret_cast<const float4*>(&g_k[base]);
                vv = *reinterpret_cast<const float4*>(&g_v[base]);
            }
            *reinterpret_cast<float4*>(&sK[r * SKV_STR + d]) =
                make_float4(to_tf32(kv.x), to_tf32(kv.y), to_tf32(kv.z), to_tf32(kv.w));
            *reinterpret_cast<float4*>(&sV[r * SKV_STR + d]) =
                make_float4(to_tf32(vv.x), to_tf32(vv.y), to_tf32(vv.z), to_tf32(vv.w));
        }
        __syncthreads();

        // ---- S = Q K^T (ks-outer: 8 independent accumulators) ----
        float sfr[8][4];
#pragma unroll
        for (int nt = 0; nt < 8; nt++)
#pragma unroll
            for (int j = 0; j < 4; j++) sfr[nt][j] = 0.f;

#pragma unroll
        for (int ks = 0; ks < 8; ks++) {
#pragma unroll
            for (int nt = 0; nt < 8; nt++) {
                const float* bp = &sK[(nt * 8 + gr) * SKV_STR + ks * 8 + c];
                mma_tf32(sfr[nt], qf[ks],
                         __float_as_uint(bp[0]), __float_as_uint(bp[4]));
            }
        }

        // ---- scale + mask + warp-local online softmax ----
        float tmax0 = -INFINITY, tmax1 = -INFINITY;
#pragma unroll
        for (int nt = 0; nt < 8; nt++) {
            int col = nt * 8 + 2 * c;
            float s0 = sfr[nt][0] * scale, s1 = sfr[nt][1] * scale;
            float s2 = sfr[nt][2] * scale, s3 = sfr[nt][3] * scale;
            if (col     >= valid) { s0 = -1e30f; s2 = -1e30f; }
            if (col + 1 >= valid) { s1 = -1e30f; s3 = -1e30f; }
            sfr[nt][0] = s0; sfr[nt][1] = s1; sfr[nt][2] = s2; sfr[nt][3] = s3;
            tmax0 = fmaxf(tmax0, fmaxf(s0, s1));
            tmax1 = fmaxf(tmax1, fmaxf(s2, s3));
        }
        tmax0 = fmaxf(tmax0, __shfl_xor_sync(0xFFFFFFFFu, tmax0, 1));
        tmax0 = fmaxf(tmax0, __shfl_xor_sync(0xFFFFFFFFu, tmax0, 2));
        tmax1 = fmaxf(tmax1, __shfl_xor_sync(0xFFFFFFFFu, tmax1, 1));
        tmax1 = fmaxf(tmax1, __shfl_xor_sync(0xFFFFFFFFu, tmax1, 2));

        float mn0 = fmaxf(m0, tmax0), mn1 = fmaxf(m1, tmax1);
        float corr0 = __expf(m0 - mn0), corr1 = __expf(m1 - mn1);
        m0 = mn0; m1 = mn1;

        float ps0 = 0.f, ps1 = 0.f;
#pragma unroll
        for (int nt = 0; nt < 8; nt++) {
            float p0 = __expf(sfr[nt][0] - mn0);
            float p1 = __expf(sfr[nt][1] - mn0);
            float p2 = __expf(sfr[nt][2] - mn1);
            float p3 = __expf(sfr[nt][3] - mn1);
            sfr[nt][0] = p0; sfr[nt][1] = p1; sfr[nt][2] = p2; sfr[nt][3] = p3;
            ps0 += p0 + p1; ps1 += p2 + p3;
        }
        ps0 += __shfl_xor_sync(0xFFFFFFFFu, ps0, 1);
        ps0 += __shfl_xor_sync(0xFFFFFFFFu, ps0, 2);
        ps1 += __shfl_xor_sync(0xFFFFFFFFu, ps1, 1);
        ps1 += __shfl_xor_sync(0xFFFFFFFFu, ps1, 2);
        l0 = l0 * corr0 + ps0;
        l1 = l1 * corr1 + ps1;

#pragma unroll
        for (int nt = 0; nt < 8; nt++) {
            o[nt][0] *= corr0; o[nt][1] *= corr0;
            o[nt][2] *= corr1; o[nt][3] *= corr1;
        }

        // ---- spill P (tf32) to warp-private smem ----
        {
            float* pr0 = &sP[(warp * 16 + gr) * SQ_STR];
            float* pr1 = &sP[(warp * 16 + gr + 8) * SQ_STR];
#pragma unroll
            for (int nt = 0; nt < 8; nt++) {
                int col = nt * 8 + 2 * c;
                *reinterpret_cast<float2*>(pr0 + col) =
                    make_float2(to_tf32(sfr[nt][0]), to_tf32(sfr[nt][1]));
                *reinterpret_cast<float2*>(pr1 + col) =
                    make_float2(to_tf32(sfr[nt][2]), to_tf32(sfr[nt][3]));
            }
        }
        __syncwarp();

        // ---- O += P V (ks-outer, independent nt accumulators) ----
#pragma unroll
        for (int ks = 0; ks < 8; ks++) {
            const float* ap = &sP[(warp * 16 + gr) * SQ_STR + ks * 8 + c];
            uint32_t a[4];
            a[0] = __float_as_uint(ap[0]);
            a[1] = __float_as_uint(ap[8 * SQ_STR]);
            a[2] = __float_as_uint(ap[4]);
            a[3] = __float_as_uint(ap[8 * SQ_STR + 4]);
#pragma unroll
            for (int nt = 0; nt < 8; nt++) {
                const float* bp = &sV[(ks * 8 + c) * SKV_STR + nt * 8 + gr];
                mma_tf32(o[nt], a,
                         __float_as_uint(bp[0]),
                         __float_as_uint(bp[4 * SKV_STR]));
            }
        }
    }

    // ---- epilogue ----
    const int lr0 = warp * 16 + gr;
    const float inv0 = 1.f / l0, inv1 = 1.f / l1;
#pragma unroll
    for (int nt = 0; nt < 8; nt++) {
        int col = h * HD + nt * 8 + 2 * c;
        if (lr0 < QT)
            *reinterpret_cast<float2*>(&g_att[(qbase + lr0) * DIM + col]) =
                make_float2(o[nt][0] * inv0, o[nt][1] * inv0);
        if (lr0 + 8 < QT)
            *reinterpret_cast<float2*>(&g_att[(qbase + lr0 + 8) * DIM + col]) =
                make_float2(o[nt][2] * inv1, o[nt][3] * inv1);
    }
}

// ---------------------------------------------------------------------------
extern "C" void kernel_launch(void* const* d_in, const int* in_sizes, int n_in,
                              void* d_out, int out_size) {
    const float* xq  = (const float*)d_in[0];
    const float* xk  = (const float*)d_in[1];
    const float* pos = (const float*)d_in[2];
    const int*   channels = (const int*)d_in[3];
    const float* Wq = (const float*)d_in[4];  const float* bq = (const float*)d_in[5];
    const float* Wk = (const float*)d_in[6];  const float* bk = (const float*)d_in[7];
    const float* Wv = (const float*)d_in[8];  const float* bv = (const float*)d_in[9];
    const float* Wo = (const float*)d_in[10]; const float* bo = (const float*)d_in[11];

    cudaFuncSetAttribute(attn5, cudaFuncAttributeMaxDynamicSharedMemorySize,
                         A5_SMEM_BYTES);

    const int gy = (T_TOK + BM - 1) / BM;   // 25
    proj_qkv<<<dim3(DIM / BN, gy, 3), 256>>>(xq, xk, pos, Wq, bq, Wk, bk, Wv, bv);
    attn5<<<dim3(NTILES, NH), 128, A5_SMEM_BYTES>>>(channels);
    proj_o<<<dim3(DIM / BN, gy, 1), 256>>>(Wo, bo, (float*)d_out);
}